// round 14
// baseline (speedup 1.0000x reference)
#include <cuda_runtime.h>
#include <cstdint>

// 2-layer LSTM, H=6, F=6, B=4096, T=1024.
// R9 core (best, 226us) + temporal dual-stepping:
// each warp owns 4 elements as two independent pairs A={b0,b0+1}, B={b0+2,b0+3}.
// Lane (e,l,k) runs the SAME weights for its A-element and B-element; per loop
// iteration stepA and stepB execute back-to-back -> two fully independent
// dependency chains in flight per warp (double ILP), one syncwarp per 2 steps.
// K-packed f32x2 matvec, smem h-exchange (double-buffered slots), tanh.approx.

#define WPB 7
#define THREADS (WPB * 32)
#define T_LEN 1024
#define TCHUNK 16
#define NCHUNK (T_LEN / TCHUNK)     // 64
#define CSTRIDE 104                 // floats per elem per chunk (96 data + 8 pad)
#define CSTRIDE4 (CSTRIDE / 4)      // 26

typedef unsigned long long ull;

__device__ __forceinline__ float tanha(float x) {
    float y; asm("tanh.approx.f32 %0, %1;" : "=f"(y) : "f"(x)); return y;
}
__device__ __forceinline__ ull pk2(float lo, float hi) {
    ull r; asm("mov.b64 %0, {%1, %2};" : "=l"(r) : "f"(lo), "f"(hi)); return r;
}
__device__ __forceinline__ void upk2(float& lo, float& hi, ull v) {
    asm("mov.b64 {%0, %1}, %2;" : "=f"(lo), "=f"(hi) : "l"(v));
}
__device__ __forceinline__ ull fma2(ull a, ull b, ull c) {
    ull d; asm("fma.rn.f32x2 %0, %1, %2, %3;" : "=l"(d) : "l"(a), "l"(b), "l"(c));
    return d;
}
__device__ __forceinline__ ull lds64(uint32_t addr) {
    ull v; asm volatile("ld.shared.b64 %0, [%1];" : "=l"(v) : "r"(addr));
    return v;
}
__device__ __forceinline__ void sts32(uint32_t addr, float v) {
    asm volatile("st.shared.f32 [%0], %1;" :: "r"(addr), "f"(v) : "memory");
}

__global__ __launch_bounds__(THREADS, 1)
void lstm2_kernel(const float* __restrict__ x,
                  const float* __restrict__ wih0, const float* __restrict__ whh0,
                  const float* __restrict__ bih0, const float* __restrict__ bhh0,
                  const float* __restrict__ wih1, const float* __restrict__ whh1,
                  const float* __restrict__ bih1, const float* __restrict__ bhh1,
                  float* __restrict__ out, int B)
{
    __shared__ float sx[2][WPB][4 * CSTRIDE];   // x staging: 4 elems per warp
    __shared__ float soB[WPB][4 * CSTRIDE];     // h1 output staging
    __shared__ float hx[WPB][192];              // h-exchange: set A [0:96), set B [96:192)

    const int lane = threadIdx.x & 31;
    const int warp = threadIdx.x >> 5;
    const int e    = lane >> 4;
    const int s    = lane & 15;
    const int l    = (s >= 6 && s < 12) ? 1 : 0;
    const int k    = (s < 6) ? s : ((s < 12) ? s - 6 : 0);
    const bool wr  = (s >= 6 && s < 12);

    const int b0 = (blockIdx.x * WPB + warp) * 4;
    if (b0 >= B) return;

    // ---- K-packed per-lane weights (shared by A and B elements) ----
    const float* wih = l ? wih1 : wih0;
    const float* whh = l ? whh1 : whh0;
    const float* bih = l ? bih1 : bih0;
    const float* bhh = l ? bhh1 : bhh0;

    ull wx[4][3], wh[4][3], bz[4];
#pragma unroll
    for (int g = 0; g < 4; g++) {
        const float sc = (g == 2) ? 1.0f : 0.5f;
        const int row = g * 6 + k;
#pragma unroll
        for (int p = 0; p < 3; p++) {
            wx[g][p] = pk2(wih[row * 6 + 2 * p] * sc, wih[row * 6 + 2 * p + 1] * sc);
            wh[g][p] = pk2(whh[row * 6 + 2 * p] * sc, whh[row * 6 + 2 * p + 1] * sc);
        }
        bz[g] = pk2((bih[row] + bhh[row]) * sc, 0.0f);
    }

    // ---- smem addresses (two independent h-exchange sets) ----
    const uint32_t hx_u  = (uint32_t)__cvta_generic_to_shared(&hx[warp][0]);
    const uint32_t hxeA  = hx_u + e * 192;             // set A, this elem-slot
    const uint32_t hxeB  = hxeA + 384;                 // set B
    const uint32_t recOA = hxeA + l * 32, recEA = recOA + 80;
    const uint32_t recOB = hxeB + l * 32, recEB = recOB + 80;
    const uint32_t stOA  = hxeA + ((s < 12) ? (l * 8 + k) * 4 : 56), stEA = stOA + 80;
    const uint32_t stOB  = hxeB + ((s < 12) ? (l * 8 + k) * 4 : 56), stEB = stOB + 80;
    uint32_t sx_u[2];
    sx_u[0] = (uint32_t)__cvta_generic_to_shared(&sx[0][warp][0]);
    sx_u[1] = (uint32_t)__cvta_generic_to_shared(&sx[1][warp][0]);
    const uint32_t so_u = (uint32_t)__cvta_generic_to_shared(&soB[warp][0]);
    const uint32_t oaA  = so_u + (uint32_t)(e * CSTRIDE + k) * 4;          // + dt*24
    const uint32_t oaB  = oaA + 2 * CSTRIDE * 4;

    // zero both h-exchange sets (192 floats, 6 per lane)
#pragma unroll
    for (int i = 0; i < 6; i++) hx[warp][i * 32 + lane] = 0.0f;
    __syncwarp();

    float ccA = 0.0f, ccB = 0.0f;

    auto stage = [&](int c, int buf) {
        float4* dst = reinterpret_cast<float4*>(sx[buf][warp]);
#pragma unroll
        for (int i = 0; i < 3; i++) {             // 96 float4 per warp
            int idx = i * 32 + lane;
            int ee  = idx / 24;
            int off = idx - ee * 24;
            const float4* src = reinterpret_cast<const float4*>(
                x + (size_t)(b0 + ee) * (T_LEN * 6) + c * (TCHUNK * 6));
            dst[ee * CSTRIDE4 + off] = src[off];
        }
    };

    // one LSTM step (no sync): ia=input addr, ra=rec addr, wa=h write addr,
    // cc=cell state ref, oa=output staging addr (0 -> prologue, no store)
    auto step = [&](uint32_t ia, uint32_t ra, uint32_t wa, float& cc, uint32_t oa) {
        const ull v0 = lds64(ia), v1 = lds64(ia + 8), v2 = lds64(ia + 16);
        const ull r0 = lds64(ra), r1 = lds64(ra + 8), r2 = lds64(ra + 16);

        ull z0 = fma2(wx[0][0], v0, bz[0]);
        ull z1 = fma2(wx[1][0], v0, bz[1]);
        ull z2 = fma2(wx[2][0], v0, bz[2]);
        ull z3 = fma2(wx[3][0], v0, bz[3]);
        z0 = fma2(wx[0][1], v1, z0); z1 = fma2(wx[1][1], v1, z1);
        z2 = fma2(wx[2][1], v1, z2); z3 = fma2(wx[3][1], v1, z3);
        z0 = fma2(wx[0][2], v2, z0); z1 = fma2(wx[1][2], v2, z1);
        z2 = fma2(wx[2][2], v2, z2); z3 = fma2(wx[3][2], v2, z3);
        z0 = fma2(wh[0][0], r0, z0); z1 = fma2(wh[1][0], r0, z1);
        z2 = fma2(wh[2][0], r0, z2); z3 = fma2(wh[3][0], r0, z3);
        z0 = fma2(wh[0][1], r1, z0); z1 = fma2(wh[1][1], r1, z1);
        z2 = fma2(wh[2][1], r1, z2); z3 = fma2(wh[3][1], r1, z3);
        z0 = fma2(wh[0][2], r2, z0); z1 = fma2(wh[1][2], r2, z1);
        z2 = fma2(wh[2][2], r2, z2); z3 = fma2(wh[3][2], r2, z3);

        float a, b2;
        upk2(a, b2, z0); const float zi = a + b2;
        upk2(a, b2, z1); const float zf = a + b2;
        upk2(a, b2, z2); const float zg = a + b2;
        upk2(a, b2, z3); const float zo = a + b2;

        const float gi = fmaf(0.5f, tanha(zi), 0.5f);
        const float gf = fmaf(0.5f, tanha(zf), 0.5f);
        const float gg = tanha(zg);
        const float go = fmaf(0.5f, tanha(zo), 0.5f);

        cc = fmaf(gf, cc, gi * gg);
        const float hn = go * tanha(cc);

        sts32(wa, hn);
        if (oa != 0 && wr) sts32(oa, hn);
    };

    // ---- prologue: stage chunk 0; step 0 (layer0 t=0) for A and B ----
    stage(0, 0);
    __syncwarp();
    {
        const uint32_t iaA = l ? hxeA : (sx_u[0] + e * (CSTRIDE * 4));
        const uint32_t iaB = l ? hxeB : (sx_u[0] + (2 + e) * (CSTRIDE * 4));
        step(iaA, recOA, stEA, ccA, 0);
        step(iaB, recOB, stEB, ccB, 0);
        if (l) { ccA = 0.0f; ccB = 0.0f; sts32(stEA, 0.0f); sts32(stEB, 0.0f); }
        __syncwarp();
    }

    // ---- main loop: chunk c covers main steps m = c*16+1 .. c*16+16 ----
    for (int c = 0; c < NCHUNK; c++) {
        if (c + 1 < NCHUNK) stage(c + 1, (c + 1) & 1);
        __syncwarp();

        const uint32_t xbA = sx_u[c & 1] + e * (CSTRIDE * 4);
        const uint32_t xnA = sx_u[(c + 1) & 1] + e * (CSTRIDE * 4);
        const uint32_t xbB = xbA + 2 * CSTRIDE * 4;
        const uint32_t xnB = xnA + 2 * CSTRIDE * 4;

        uint32_t inpEA = l ? (hxeA + 80) : (xbA + 24);
        uint32_t inpOA = l ? (hxeA +  0) : (xbA + 48);
        uint32_t inpEB = l ? (hxeB + 80) : (xbB + 24);
        uint32_t inpOB = l ? (hxeB +  0) : (xbB + 48);
        const uint32_t inpLastA = l ? hxeA : xnA;
        const uint32_t inpLastB = l ? hxeB : xnB;
        const uint32_t sI = l ? 0u : 48u;

#pragma unroll
        for (int dt = 0; dt < TCHUNK; dt += 2) {
            // even dt: read slot1, write slot0  (A then B, one sync)
            step(inpEA, recEA, stOA, ccA, oaA + (uint32_t)dt * 24);
            step(inpEB, recEB, stOB, ccB, oaB + (uint32_t)dt * 24);
            __syncwarp();
            // odd dt: read slot0, write slot1
            const uint32_t iaA = (dt + 1 == TCHUNK - 1) ? inpLastA : inpOA;
            const uint32_t iaB = (dt + 1 == TCHUNK - 1) ? inpLastB : inpOB;
            step(iaA, recOA, stEA, ccA, oaA + (uint32_t)(dt + 1) * 24);
            step(iaB, recOB, stEB, ccB, oaB + (uint32_t)(dt + 1) * 24);
            __syncwarp();
            inpEA += sI; inpOA += sI; inpEB += sI; inpOB += sI;
        }

        // ---- flush h1 outputs for t in [c*16, c*16+16), 4 elements ----
        {
            const float4* src = reinterpret_cast<const float4*>(soB[warp]);
#pragma unroll
            for (int i = 0; i < 3; i++) {
                int idx = i * 32 + lane;
                int ee  = idx / 24;
                int off = idx - ee * 24;
                float4* dst = reinterpret_cast<float4*>(
                    out + (size_t)(b0 + ee) * (T_LEN * 6) + c * (TCHUNK * 6));
                dst[off] = src[ee * CSTRIDE4 + off];
            }
        }
        __syncwarp();
    }
}

extern "C" void kernel_launch(void* const* d_in, const int* in_sizes, int n_in,
                              void* d_out, int out_size)
{
    const float* x    = (const float*)d_in[0];
    const float* wih0 = (const float*)d_in[1];
    const float* whh0 = (const float*)d_in[2];
    const float* bih0 = (const float*)d_in[3];
    const float* bhh0 = (const float*)d_in[4];
    const float* wih1 = (const float*)d_in[5];
    const float* whh1 = (const float*)d_in[6];
    const float* bih1 = (const float*)d_in[7];
    const float* bhh1 = (const float*)d_in[8];
    float* out = (float*)d_out;

    const int B = in_sizes[0] / (T_LEN * 6);                 // 4096
    const int grid = (B + 4 * WPB - 1) / (4 * WPB);          // 147

    lstm2_kernel<<<grid, THREADS>>>(x, wih0, whh0, bih0, bhh0,
                                    wih1, whh1, bih1, bhh1, out, B);
}

// round 15
// speedup vs baseline: 1.0455x; 1.0455x over previous
#include <cuda_runtime.h>
#include <cstdint>

// 2-layer LSTM, H=6, F=6, B=4096, T=1024.
// R14 dual-element structure (4 elems/warp as two independent sets A/B) with
// the serialization bug fixed: each iteration is
//   [12x LDS (A+B inputs+rec, no chain deps)] -> [two pure fma2/tanh chains,
//   interleaved by ptxas] -> [STS x2 + output STS] -> [one syncwarp].
// Previously (R14) B's loads were volatile-ordered AFTER A's dependent STS,
// fully serializing the two chains. Hoisting all loads above both chains
// restores the intended 2x ILP and halves sync count per step.
// K-packed f32x2 matvec, smem h-exchange (double-buffered slots), tanh.approx.

#define WPB 7
#define THREADS (WPB * 32)
#define T_LEN 1024
#define TCHUNK 16
#define NCHUNK (T_LEN / TCHUNK)     // 64
#define CSTRIDE 104                 // floats per elem per chunk (96 data + 8 pad)
#define CSTRIDE4 (CSTRIDE / 4)      // 26

typedef unsigned long long ull;

__device__ __forceinline__ float tanha(float x) {
    float y; asm("tanh.approx.f32 %0, %1;" : "=f"(y) : "f"(x)); return y;
}
__device__ __forceinline__ ull pk2(float lo, float hi) {
    ull r; asm("mov.b64 %0, {%1, %2};" : "=l"(r) : "f"(lo), "f"(hi)); return r;
}
__device__ __forceinline__ void upk2(float& lo, float& hi, ull v) {
    asm("mov.b64 {%0, %1}, %2;" : "=f"(lo), "=f"(hi) : "l"(v));
}
__device__ __forceinline__ ull fma2(ull a, ull b, ull c) {
    ull d; asm("fma.rn.f32x2 %0, %1, %2, %3;" : "=l"(d) : "l"(a), "l"(b), "l"(c));
    return d;
}
__device__ __forceinline__ ull lds64(uint32_t addr) {
    ull v; asm volatile("ld.shared.b64 %0, [%1];" : "=l"(v) : "r"(addr));
    return v;
}
__device__ __forceinline__ void sts32(uint32_t addr, float v) {
    asm volatile("st.shared.f32 [%0], %1;" :: "r"(addr), "f"(v) : "memory");
}

__global__ __launch_bounds__(THREADS, 1)
void lstm2_kernel(const float* __restrict__ x,
                  const float* __restrict__ wih0, const float* __restrict__ whh0,
                  const float* __restrict__ bih0, const float* __restrict__ bhh0,
                  const float* __restrict__ wih1, const float* __restrict__ whh1,
                  const float* __restrict__ bih1, const float* __restrict__ bhh1,
                  float* __restrict__ out, int B)
{
    __shared__ float sx[2][WPB][4 * CSTRIDE];   // x staging: 4 elems per warp
    __shared__ float soB[WPB][4 * CSTRIDE];     // h1 output staging
    __shared__ float hx[WPB][192];              // h-exchange: set A [0:96), set B [96:192)

    const int lane = threadIdx.x & 31;
    const int warp = threadIdx.x >> 5;
    const int e    = lane >> 4;
    const int s    = lane & 15;
    const int l    = (s >= 6 && s < 12) ? 1 : 0;
    const int k    = (s < 6) ? s : ((s < 12) ? s - 6 : 0);
    const bool wr  = (s >= 6 && s < 12);

    const int b0 = (blockIdx.x * WPB + warp) * 4;
    if (b0 >= B) return;

    // ---- K-packed per-lane weights (shared by A and B elements) ----
    const float* wih = l ? wih1 : wih0;
    const float* whh = l ? whh1 : whh0;
    const float* bih = l ? bih1 : bih0;
    const float* bhh = l ? bhh1 : bhh0;

    ull wx[4][3], wh[4][3], bz[4];
#pragma unroll
    for (int g = 0; g < 4; g++) {
        const float sc = (g == 2) ? 1.0f : 0.5f;
        const int row = g * 6 + k;
#pragma unroll
        for (int p = 0; p < 3; p++) {
            wx[g][p] = pk2(wih[row * 6 + 2 * p] * sc, wih[row * 6 + 2 * p + 1] * sc);
            wh[g][p] = pk2(whh[row * 6 + 2 * p] * sc, whh[row * 6 + 2 * p + 1] * sc);
        }
        bz[g] = pk2((bih[row] + bhh[row]) * sc, 0.0f);
    }

    // ---- smem addresses (two independent h-exchange sets) ----
    const uint32_t hx_u  = (uint32_t)__cvta_generic_to_shared(&hx[warp][0]);
    const uint32_t hxeA  = hx_u + e * 192;             // set A, this elem-slot
    const uint32_t hxeB  = hxeA + 384;                 // set B
    const uint32_t recOA = hxeA + l * 32, recEA = recOA + 80;
    const uint32_t recOB = hxeB + l * 32, recEB = recOB + 80;
    const uint32_t stOA  = hxeA + ((s < 12) ? (l * 8 + k) * 4 : 56), stEA = stOA + 80;
    const uint32_t stOB  = hxeB + ((s < 12) ? (l * 8 + k) * 4 : 56), stEB = stOB + 80;
    uint32_t sx_u[2];
    sx_u[0] = (uint32_t)__cvta_generic_to_shared(&sx[0][warp][0]);
    sx_u[1] = (uint32_t)__cvta_generic_to_shared(&sx[1][warp][0]);
    const uint32_t so_u = (uint32_t)__cvta_generic_to_shared(&soB[warp][0]);
    const uint32_t oaA  = so_u + (uint32_t)(e * CSTRIDE + k) * 4;          // + dt*24
    const uint32_t oaB  = oaA + 2 * CSTRIDE * 4;

    // zero both h-exchange sets (192 floats, 6 per lane)
#pragma unroll
    for (int i = 0; i < 6; i++) hx[warp][i * 32 + lane] = 0.0f;
    __syncwarp();

    float ccA = 0.0f, ccB = 0.0f;

    auto stage = [&](int c, int buf) {
        float4* dst = reinterpret_cast<float4*>(sx[buf][warp]);
#pragma unroll
        for (int i = 0; i < 3; i++) {             // 96 float4 per warp
            int idx = i * 32 + lane;
            int ee  = idx / 24;
            int off = idx - ee * 24;
            const float4* src = reinterpret_cast<const float4*>(
                x + (size_t)(b0 + ee) * (T_LEN * 6) + c * (TCHUNK * 6));
            dst[ee * CSTRIDE4 + off] = src[off];
        }
    };

    // pure-arithmetic gate block (no memory ops -> ptxas interleaves A and B)
    auto gates = [&](ull v0, ull v1, ull v2, ull r0, ull r1, ull r2,
                     float& cc) -> float {
        ull z0 = fma2(wx[0][0], v0, bz[0]);
        ull z1 = fma2(wx[1][0], v0, bz[1]);
        ull z2 = fma2(wx[2][0], v0, bz[2]);
        ull z3 = fma2(wx[3][0], v0, bz[3]);
        z0 = fma2(wx[0][1], v1, z0); z1 = fma2(wx[1][1], v1, z1);
        z2 = fma2(wx[2][1], v1, z2); z3 = fma2(wx[3][1], v1, z3);
        z0 = fma2(wx[0][2], v2, z0); z1 = fma2(wx[1][2], v2, z1);
        z2 = fma2(wx[2][2], v2, z2); z3 = fma2(wx[3][2], v2, z3);
        z0 = fma2(wh[0][0], r0, z0); z1 = fma2(wh[1][0], r0, z1);
        z2 = fma2(wh[2][0], r0, z2); z3 = fma2(wh[3][0], r0, z3);
        z0 = fma2(wh[0][1], r1, z0); z1 = fma2(wh[1][1], r1, z1);
        z2 = fma2(wh[2][1], r1, z2); z3 = fma2(wh[3][1], r1, z3);
        z0 = fma2(wh[0][2], r2, z0); z1 = fma2(wh[1][2], r2, z1);
        z2 = fma2(wh[2][2], r2, z2); z3 = fma2(wh[3][2], r2, z3);

        float a, b2;
        upk2(a, b2, z0); const float zi = a + b2;
        upk2(a, b2, z1); const float zf = a + b2;
        upk2(a, b2, z2); const float zg = a + b2;
        upk2(a, b2, z3); const float zo = a + b2;

        const float gi = fmaf(0.5f, tanha(zi), 0.5f);
        const float gf = fmaf(0.5f, tanha(zf), 0.5f);
        const float gg = tanha(zg);
        const float go = fmaf(0.5f, tanha(zo), 0.5f);

        cc = fmaf(gf, cc, gi * gg);
        return go * tanha(cc);
    };

    // one dual iteration: LOAD(A+B) -> COMPUTE(A || B) -> STORE -> sync
    auto dual = [&](uint32_t iaA, uint32_t raA, uint32_t waA,
                    uint32_t iaB, uint32_t raB, uint32_t waB, int dt) {
        // ---- load phase: 12 back-to-back LDS, no chain dependency ----
        const ull vA0 = lds64(iaA), vA1 = lds64(iaA + 8), vA2 = lds64(iaA + 16);
        const ull rA0 = lds64(raA), rA1 = lds64(raA + 8), rA2 = lds64(raA + 16);
        const ull vB0 = lds64(iaB), vB1 = lds64(iaB + 8), vB2 = lds64(iaB + 16);
        const ull rB0 = lds64(raB), rB1 = lds64(raB + 8), rB2 = lds64(raB + 16);

        // ---- compute phase: two independent chains ----
        const float hnA = gates(vA0, vA1, vA2, rA0, rA1, rA2, ccA);
        const float hnB = gates(vB0, vB1, vB2, rB0, rB1, rB2, ccB);

        // ---- store phase ----
        sts32(waA, hnA);
        sts32(waB, hnB);
        if (dt >= 0 && wr) {
            sts32(oaA + (uint32_t)dt * 24, hnA);
            sts32(oaB + (uint32_t)dt * 24, hnB);
        }
        __syncwarp();
    };

    // ---- prologue: stage chunk 0; step 0 (layer0 t=0) for A and B ----
    stage(0, 0);
    __syncwarp();
    {
        const uint32_t iaA = l ? hxeA : (sx_u[0] + e * (CSTRIDE * 4));
        const uint32_t iaB = l ? hxeB : (sx_u[0] + (2 + e) * (CSTRIDE * 4));
        dual(iaA, recOA, stEA, iaB, recOB, stEB, -1);
        if (l) { ccA = 0.0f; ccB = 0.0f; sts32(stEA, 0.0f); sts32(stEB, 0.0f); }
        __syncwarp();
    }

    // ---- main loop: chunk c covers main steps m = c*16+1 .. c*16+16 ----
    for (int c = 0; c < NCHUNK; c++) {
        if (c + 1 < NCHUNK) stage(c + 1, (c + 1) & 1);
        __syncwarp();

        const uint32_t xbA = sx_u[c & 1] + e * (CSTRIDE * 4);
        const uint32_t xnA = sx_u[(c + 1) & 1] + e * (CSTRIDE * 4);
        const uint32_t xbB = xbA + 2 * CSTRIDE * 4;
        const uint32_t xnB = xnA + 2 * CSTRIDE * 4;

        uint32_t inpEA = l ? (hxeA + 80) : (xbA + 24);
        uint32_t inpOA = l ? (hxeA +  0) : (xbA + 48);
        uint32_t inpEB = l ? (hxeB + 80) : (xbB + 24);
        uint32_t inpOB = l ? (hxeB +  0) : (xbB + 48);
        const uint32_t inpLastA = l ? hxeA : xnA;
        const uint32_t inpLastB = l ? hxeB : xnB;
        const uint32_t sI = l ? 0u : 48u;

#pragma unroll
        for (int dt = 0; dt < TCHUNK; dt += 2) {
            // even dt: read slot1, write slot0
            dual(inpEA, recEA, stOA, inpEB, recEB, stOB, dt);
            // odd dt: read slot0, write slot1
            const uint32_t iaA = (dt + 1 == TCHUNK - 1) ? inpLastA : inpOA;
            const uint32_t iaB = (dt + 1 == TCHUNK - 1) ? inpLastB : inpOB;
            dual(iaA, recOA, stEA, iaB, recOB, stEB, dt + 1);
            inpEA += sI; inpOA += sI; inpEB += sI; inpOB += sI;
        }

        // ---- flush h1 outputs for t in [c*16, c*16+16), 4 elements ----
        {
            const float4* src = reinterpret_cast<const float4*>(soB[warp]);
#pragma unroll
            for (int i = 0; i < 3; i++) {
                int idx = i * 32 + lane;
                int ee  = idx / 24;
                int off = idx - ee * 24;
                float4* dst = reinterpret_cast<float4*>(
                    out + (size_t)(b0 + ee) * (T_LEN * 6) + c * (TCHUNK * 6));
                dst[off] = src[ee * CSTRIDE4 + off];
            }
        }
        __syncwarp();
    }
}

extern "C" void kernel_launch(void* const* d_in, const int* in_sizes, int n_in,
                              void* d_out, int out_size)
{
    const float* x    = (const float*)d_in[0];
    const float* wih0 = (const float*)d_in[1];
    const float* whh0 = (const float*)d_in[2];
    const float* bih0 = (const float*)d_in[3];
    const float* bhh0 = (const float*)d_in[4];
    const float* wih1 = (const float*)d_in[5];
    const float* whh1 = (const float*)d_in[6];
    const float* bih1 = (const float*)d_in[7];
    const float* bhh1 = (const float*)d_in[8];
    float* out = (float*)d_out;

    const int B = in_sizes[0] / (T_LEN * 6);                 // 4096
    const int grid = (B + 4 * WPB - 1) / (4 * WPB);          // 147

    lstm2_kernel<<<grid, THREADS>>>(x, wih0, whh0, bih0, bhh0,
                                    wih1, whh1, bih1, bhh1, out, B);
}

// round 16
// speedup vs baseline: 1.2305x; 1.1770x over previous
#include <cuda_runtime.h>
#include <cstdint>

// 2-layer LSTM, H=6, F=6, B=4096, T=1024.  R9 (best, 226us) with ONE change:
// the per-step __syncwarp() is removed. The step body is branch-free (no
// divergence possible), all smem ops are volatile asm (fixed compile order),
// and a warp issues smem ops in program order -> the next step's rec-LDS
// (issued after this step's h-STS) observes the store without a barrier.
// This removes ~23+ cyc of WARPSYNC + STS-drain from every one of 1024 steps
// and removes the per-step convergence point that clusters warp stalls.
// Layout: 2 elems/warp, 12 active lanes/elem: lane (l,k) owns hidden k of
// layer l; K-packed f32x2 matvec; smem h-exchange (double-buffered slots);
// tanh.approx activations (sigmoid = 0.5*tanh(z/2)+0.5 folded into weights).
// Pipelined: main step m computes layer0(t=m) and layer1(t=m-1).

#define WARPS_PER_BLOCK 14
#define THREADS (WARPS_PER_BLOCK * 32)
#define T_LEN 1024
#define TCHUNK 16
#define NCHUNK (T_LEN / TCHUNK)     // 64
#define CSTRIDE 104                 // floats per elem per chunk (96 data + 8 pad)
#define CSTRIDE4 (CSTRIDE / 4)      // 26

typedef unsigned long long ull;

__device__ __forceinline__ float tanha(float x) {
    float y; asm("tanh.approx.f32 %0, %1;" : "=f"(y) : "f"(x)); return y;
}
__device__ __forceinline__ ull pk2(float lo, float hi) {
    ull r; asm("mov.b64 %0, {%1, %2};" : "=l"(r) : "f"(lo), "f"(hi)); return r;
}
__device__ __forceinline__ void upk2(float& lo, float& hi, ull v) {
    asm("mov.b64 {%0, %1}, %2;" : "=f"(lo), "=f"(hi) : "l"(v));
}
__device__ __forceinline__ ull fma2(ull a, ull b, ull c) {
    ull d; asm("fma.rn.f32x2 %0, %1, %2, %3;" : "=l"(d) : "l"(a), "l"(b), "l"(c));
    return d;
}
__device__ __forceinline__ ull lds64(uint32_t addr) {
    ull v; asm volatile("ld.shared.b64 %0, [%1];" : "=l"(v) : "r"(addr));
    return v;
}
__device__ __forceinline__ void sts32(uint32_t addr, float v) {
    asm volatile("st.shared.f32 [%0], %1;" :: "r"(addr), "f"(v) : "memory");
}

__global__ __launch_bounds__(THREADS, 1)
void lstm2_kernel(const float* __restrict__ x,
                  const float* __restrict__ wih0, const float* __restrict__ whh0,
                  const float* __restrict__ bih0, const float* __restrict__ bhh0,
                  const float* __restrict__ wih1, const float* __restrict__ whh1,
                  const float* __restrict__ bih1, const float* __restrict__ bhh1,
                  float* __restrict__ out, int B)
{
    __shared__ float sx[2][WARPS_PER_BLOCK][2 * CSTRIDE];
    __shared__ float soB[WARPS_PER_BLOCK][2 * CSTRIDE];
    __shared__ float hx[WARPS_PER_BLOCK][96];   // e*48 + slot*20 + l*8 + k

    const int lane = threadIdx.x & 31;
    const int warp = threadIdx.x >> 5;
    const int e    = lane >> 4;
    const int s    = lane & 15;
    const int l    = (s >= 6 && s < 12) ? 1 : 0;
    const int k    = (s < 6) ? s : ((s < 12) ? s - 6 : 0);
    const bool wr  = (s >= 6 && s < 12);

    const int b0 = (blockIdx.x * WARPS_PER_BLOCK + warp) * 2;
    if (b0 >= B) return;

    // ---- K-packed per-lane weights (4 gate rows of hidden k, layer l) ----
    const float* wih = l ? wih1 : wih0;
    const float* whh = l ? whh1 : whh0;
    const float* bih = l ? bih1 : bih0;
    const float* bhh = l ? bhh1 : bhh0;

    ull wx[4][3], wh[4][3], bz[4];
#pragma unroll
    for (int g = 0; g < 4; g++) {
        const float sc = (g == 2) ? 1.0f : 0.5f;
        const int row = g * 6 + k;
#pragma unroll
        for (int p = 0; p < 3; p++) {
            wx[g][p] = pk2(wih[row * 6 + 2 * p] * sc, wih[row * 6 + 2 * p + 1] * sc);
            wh[g][p] = pk2(whh[row * 6 + 2 * p] * sc, whh[row * 6 + 2 * p + 1] * sc);
        }
        bz[g] = pk2((bih[row] + bhh[row]) * sc, 0.0f);
    }

    // ---- smem addresses ----
    const uint32_t hx_u  = (uint32_t)__cvta_generic_to_shared(&hx[warp][0]);
    const uint32_t hxe_u = hx_u + e * 192;
    const uint32_t recO  = hxe_u + l * 32;
    const uint32_t recE  = recO + 80;
    const uint32_t stO   = hxe_u + ((s < 12) ? (l * 8 + k) * 4 : 56);
    const uint32_t stE   = stO + 80;
    uint32_t sx_u[2];
    sx_u[0] = (uint32_t)__cvta_generic_to_shared(&sx[0][warp][0]);
    sx_u[1] = (uint32_t)__cvta_generic_to_shared(&sx[1][warp][0]);

    hx[warp][lane] = 0.0f; hx[warp][lane + 32] = 0.0f; hx[warp][lane + 64] = 0.0f;
    __syncwarp();

    float cc = 0.0f;

    auto stage = [&](int c, int buf) {
        float4* dst = reinterpret_cast<float4*>(sx[buf][warp]);
#pragma unroll
        for (int i = 0; i < 2; i++) {
            int idx = i * 32 + lane;              // 48 float4 total
            if (idx < 48) {
                int ee  = idx / 24;
                int off = idx - ee * 24;
                const float4* src = reinterpret_cast<const float4*>(
                    x + (size_t)(b0 + ee) * (T_LEN * 6) + c * (TCHUNK * 6));
                dst[ee * CSTRIDE4 + off] = src[off];
            }
        }
    };

    // one step: inp addr ia, rec addr ra, write addr wa; stores h1 if dt>=0.
    // NO syncwarp: branch-free body, volatile asm, in-order smem issue ->
    // the next step's rec-LDS (after this STS) observes the store.
    auto step = [&](uint32_t ia, uint32_t ra, uint32_t wa, int dt) {
        const ull v0 = lds64(ia), v1 = lds64(ia + 8), v2 = lds64(ia + 16);
        const ull r0 = lds64(ra), r1 = lds64(ra + 8), r2 = lds64(ra + 16);

        ull z0 = fma2(wx[0][0], v0, bz[0]);
        ull z1 = fma2(wx[1][0], v0, bz[1]);
        ull z2 = fma2(wx[2][0], v0, bz[2]);
        ull z3 = fma2(wx[3][0], v0, bz[3]);
        z0 = fma2(wx[0][1], v1, z0); z1 = fma2(wx[1][1], v1, z1);
        z2 = fma2(wx[2][1], v1, z2); z3 = fma2(wx[3][1], v1, z3);
        z0 = fma2(wx[0][2], v2, z0); z1 = fma2(wx[1][2], v2, z1);
        z2 = fma2(wx[2][2], v2, z2); z3 = fma2(wx[3][2], v2, z3);
        z0 = fma2(wh[0][0], r0, z0); z1 = fma2(wh[1][0], r0, z1);
        z2 = fma2(wh[2][0], r0, z2); z3 = fma2(wh[3][0], r0, z3);
        z0 = fma2(wh[0][1], r1, z0); z1 = fma2(wh[1][1], r1, z1);
        z2 = fma2(wh[2][1], r1, z2); z3 = fma2(wh[3][1], r1, z3);
        z0 = fma2(wh[0][2], r2, z0); z1 = fma2(wh[1][2], r2, z1);
        z2 = fma2(wh[2][2], r2, z2); z3 = fma2(wh[3][2], r2, z3);

        float a, b2;
        upk2(a, b2, z0); const float zi = a + b2;
        upk2(a, b2, z1); const float zf = a + b2;
        upk2(a, b2, z2); const float zg = a + b2;
        upk2(a, b2, z3); const float zo = a + b2;

        const float gi = fmaf(0.5f, tanha(zi), 0.5f);
        const float gf = fmaf(0.5f, tanha(zf), 0.5f);
        const float gg = tanha(zg);
        const float go = fmaf(0.5f, tanha(zo), 0.5f);

        cc = fmaf(gf, cc, gi * gg);
        const float hn = go * tanha(cc);

        sts32(wa, hn);
        if (dt >= 0 && wr) soB[warp][e * CSTRIDE + dt * 6 + k] = hn;
    };

    // ---- prologue: stage chunk 0; step 0 (layer0 t=0) ----
    stage(0, 0);
    __syncwarp();
    {
        const uint32_t ia = l ? (hxe_u + 0) : (sx_u[0] + e * 416 + 0);
        step(ia, recO, stE, -1);
        if (l) { cc = 0.0f; sts32(stE, 0.0f); }
    }

    // ---- main loop: chunk c covers main steps m = c*16+1 .. c*16+16 ----
    for (int c = 0; c < NCHUNK; c++) {
        if (c + 1 < NCHUNK) stage(c + 1, (c + 1) & 1);
        __syncwarp();

        const uint32_t xb = sx_u[c & 1] + e * 416;
        const uint32_t xn = sx_u[(c + 1) & 1] + e * 416;
        uint32_t inpE = l ? (hxe_u + 80) : (xb + 24);   // even dt: read slot1
        uint32_t inpO = l ? (hxe_u +  0) : (xb + 48);   // odd dt: read slot0
        const uint32_t inpLast = l ? (hxe_u + 0) : xn;  // dt=15 reads next chunk
        const uint32_t sI = l ? 0u : 48u;

#pragma unroll
        for (int dt = 0; dt < TCHUNK; dt += 2) {
            step(inpE, recE, stO, dt);
            const uint32_t ia = (dt + 1 == TCHUNK - 1) ? inpLast : inpO;
            step(ia, recO, stE, dt + 1);
            inpE += sI; inpO += sI;
        }
        __syncwarp();

        // ---- flush h1 outputs for t in [c*16, c*16+16) ----
        {
            const float4* src = reinterpret_cast<const float4*>(soB[warp]);
#pragma unroll
            for (int i = 0; i < 2; i++) {
                int idx = i * 32 + lane;
                if (idx < 48) {
                    int ee  = idx / 24;
                    int off = idx - ee * 24;
                    float4* dst = reinterpret_cast<float4*>(
                        out + (size_t)(b0 + ee) * (T_LEN * 6) + c * (TCHUNK * 6));
                    dst[off] = src[ee * CSTRIDE4 + off];
                }
            }
        }
        __syncwarp();
    }
}

extern "C" void kernel_launch(void* const* d_in, const int* in_sizes, int n_in,
                              void* d_out, int out_size)
{
    const float* x    = (const float*)d_in[0];
    const float* wih0 = (const float*)d_in[1];
    const float* whh0 = (const float*)d_in[2];
    const float* bih0 = (const float*)d_in[3];
    const float* bhh0 = (const float*)d_in[4];
    const float* wih1 = (const float*)d_in[5];
    const float* whh1 = (const float*)d_in[6];
    const float* bih1 = (const float*)d_in[7];
    const float* bhh1 = (const float*)d_in[8];
    float* out = (float*)d_out;

    const int B = in_sizes[0] / (T_LEN * 6);                                 // 4096
    const int grid = (B + 2 * WARPS_PER_BLOCK - 1) / (2 * WARPS_PER_BLOCK);  // 147

    lstm2_kernel<<<grid, THREADS>>>(x, wih0, whh0, bih0, bhh0,
                                    wih1, whh1, bih1, bhh1, out, B);
}